// round 4
// baseline (speedup 1.0000x reference)
#include <cuda_runtime.h>

#define T 512            // threads per block = rows per block
#define RPB 512
#define NCOLS 14
#define IN_F4 (RPB * NCOLS / 4)   // 1792 float4 per block = 3.5 per thread
#define OUT_F4 (RPB * 3 / 4)      // 384 float4 per block

__global__ __launch_bounds__(T, 4)   // force <=32 regs -> 2048 threads/SM
void indicator_kernel(const float4* __restrict__ in4, float4* __restrict__ out4,
                      int nfull, int n) {
    __shared__ float s_in[RPB * NCOLS];   // 28672 B
    __shared__ float s_out[RPB * 3];      //  6144 B

    const int tid = threadIdx.x;
    const int bid = blockIdx.x;
    float4* s4 = (float4*)s_in;
    const int base = bid * IN_F4;         // max ~7.0M — fits int32

    // ---- coalesced vectorized load: 512 contiguous rows -> smem ----
    // 1792 float4 = 3 * 512 + 256
    if (bid < nfull) {
        #pragma unroll
        for (int i = 0; i < 3; i++)
            s4[tid + i * T] = in4[base + tid + i * T];
        if (tid < IN_F4 - 3 * T)          // first 256 threads take the remainder
            s4[tid + 3 * T] = in4[base + tid + 3 * T];
    } else {
        // tail block: 128 rows = 448 float4
        if (tid < 448) s4[tid] = in4[base + tid];
    }
    __syncthreads();

    // ---- per-row compute: one row per thread ----
    const int row = bid * RPB + tid;
    if (row < n) {
        const float* r = &s_in[tid * NCOLS];
        const float ha_open  = r[0];
        const float ha_close = r[1];
        const float lw       = r[5];
        const float uw       = r[6];
        const float ma       = r[8];
        const float srsi     = r[9];
        const float ssig     = r[10];
        const float bu       = r[11];
        const float bm       = r[12];
        const float bl       = r[13];

        const bool  bullish = ha_close > ha_open;
        const bool  bearish = ha_close < ha_open;
        const float body    = fabsf(ha_close - ha_open);
        const bool  sb = bullish && (body > 0.5f) && (uw < 1e-6f);  // strong_bullish
        const bool  sB = bearish && (body > 0.5f) && (lw < 1e-6f);  // strong_bearish

        const float ha2 = sb ? 0.8f : 0.0f;
        const float ha0 = sB ? 0.8f : 0.0f;

        const float width = (bu - bl) / bm;
        const float pp    = (ha_close - bl) / (bu - bl);
        // structurally false, kept for exact fidelity (NaN behavior identical):
        const bool  sqexp = (width < 0.1f) && (width > 0.2f);
        const float sqf   = sqexp ? 0.9f : 0.0f;

        const bool pp_lo = pp < 0.2f;
        const bool pp_hi = pp > 0.8f;
        const float bb2 = (pp_lo ? 0.8f : 0.0f) + sqf;
        const float bb0 = (pp_hi ? 0.8f : 0.0f) + sqf;

        const float st2 = (srsi < 0.2f) ? 0.8f : 0.0f;
        const float st0 = (srsi > 0.8f) ? 0.8f : 0.0f;

        const bool  ma_up = ma > 0.1f;
        const bool  ma_dn = ma < -0.1f;
        const float ma2 = ma_up ? 0.7f : 0.0f;
        const float ma0 = ma_dn ? 0.7f : 0.0f;

        const bool st_dn = ssig < -0.1f;
        const bool st_up = ssig > 0.1f;

        // OR of all 3-of-4 conjunctions == majority(>=3 of 4)
        const bool long_sig  = ((int)sb + (int)ma_up + (int)st_dn + (int)pp_lo) >= 3;
        const bool short_sig = ((int)sB + (int)ma_dn + (int)st_up + (int)pp_hi) >= 3;

        const float hms2 = long_sig  ? 0.9f : 0.0f;
        const float hms0 = short_sig ? 0.9f : 0.0f;

        const float col0 = ha0 + ma0 + st0 + bb0 + 2.0f * hms0;
        const float col2 = ha2 + ma2 + st2 + bb2 + 2.0f * hms2;
        const float col1 = 1.5f;

        const float m  = fmaxf(fmaxf(col0, col2), col1);
        const float e0 = __expf(col0 - m);
        const float e1 = __expf(col1 - m);
        const float e2 = __expf(col2 - m);
        const float inv = 1.0f / (e0 + e1 + e2);

        s_out[tid * 3 + 0] = e0 * inv;
        s_out[tid * 3 + 1] = e1 * inv;
        s_out[tid * 3 + 2] = e2 * inv;
    }
    __syncthreads();

    // ---- coalesced vectorized store ----
    const float4* so4 = (const float4*)s_out;
    const int obase = bid * OUT_F4;       // max 3906*384 = 1.5M
    if (bid < nfull) {
        if (tid < OUT_F4)                 // 384 of 512 threads
            out4[obase + tid] = so4[tid];
    } else {
        // tail: 128 rows -> 96 float4
        if (tid < 96) out4[obase + tid] = so4[tid];
    }
}

extern "C" void kernel_launch(void* const* d_in, const int* in_sizes, int n_in,
                              void* d_out, int out_size) {
    const float4* in4 = (const float4*)d_in[0];
    float4* out4 = (float4*)d_out;
    const int n = in_sizes[0] / NCOLS;       // 2,000,000 rows
    const int grid  = (n + RPB - 1) / RPB;   // 3907 blocks
    const int nfull = n / RPB;               // 3906 full blocks
    indicator_kernel<<<grid, T>>>(in4, out4, nfull, n);
}

// round 5
// speedup vs baseline: 1.2644x; 1.2644x over previous
#include <cuda_runtime.h>

#define T 256            // threads per block = rows per block
#define RPB 256
#define NCOLS 14
#define IN_F4 (RPB * NCOLS / 4)   // 896 float4 per block = 3 + 0.5 per thread
#define OUT_F4 (RPB * 3 / 4)      // 192 float4 per block

__global__ __launch_bounds__(T, 8)   // pin regs <=32 -> 8 CTAs/SM
void indicator_kernel(const float4* __restrict__ in4, float4* __restrict__ out4,
                      int nfull, int n) {
    __shared__ float s_in[RPB * NCOLS];   // 14336 B
    __shared__ float s_out[RPB * 3];      //  3072 B

    const int tid = threadIdx.x;
    const int bid = blockIdx.x;
    float4* s4 = (float4*)s_in;
    const int base = bid * IN_F4;         // max 7812*896 = 7.0M — fits int32

    // ---- coalesced vectorized load: 256 contiguous rows -> smem ----
    // 896 float4 = 3 * 256 + 128
    if (bid < nfull) {
        #pragma unroll
        for (int i = 0; i < 3; i++)
            s4[tid + i * T] = in4[base + tid + i * T];
        if (tid < IN_F4 - 3 * T)          // first 128 threads take the remainder
            s4[tid + 3 * T] = in4[base + tid + 3 * T];
    } else {
        // tail block: 128 rows = 448 float4
        #pragma unroll
        for (int i = 0; i < 2; i++)
            if (tid + i * T < 448) s4[tid + i * T] = in4[base + tid + i * T];
    }
    __syncthreads();

    // ---- per-row compute: one row per thread ----
    const int row = bid * RPB + tid;
    if (row < n) {
        const float* r = &s_in[tid * NCOLS];
        const float ha_open  = r[0];
        const float ha_close = r[1];
        const float lw       = r[5];
        const float uw       = r[6];
        const float ma       = r[8];
        const float srsi     = r[9];
        const float ssig     = r[10];
        const float bu       = r[11];
        const float bm       = r[12];
        const float bl       = r[13];

        const bool  bullish = ha_close > ha_open;
        const bool  bearish = ha_close < ha_open;
        const float body    = fabsf(ha_close - ha_open);
        const bool  sb = bullish && (body > 0.5f) && (uw < 1e-6f);  // strong_bullish
        const bool  sB = bearish && (body > 0.5f) && (lw < 1e-6f);  // strong_bearish

        const float ha2 = sb ? 0.8f : 0.0f;
        const float ha0 = sB ? 0.8f : 0.0f;

        const float width = (bu - bl) / bm;
        const float pp    = (ha_close - bl) / (bu - bl);
        // structurally false, kept for exact fidelity (NaN behavior identical):
        const bool  sqexp = (width < 0.1f) && (width > 0.2f);
        const float sqf   = sqexp ? 0.9f : 0.0f;

        const bool pp_lo = pp < 0.2f;
        const bool pp_hi = pp > 0.8f;
        const float bb2 = (pp_lo ? 0.8f : 0.0f) + sqf;
        const float bb0 = (pp_hi ? 0.8f : 0.0f) + sqf;

        const float st2 = (srsi < 0.2f) ? 0.8f : 0.0f;
        const float st0 = (srsi > 0.8f) ? 0.8f : 0.0f;

        const bool  ma_up = ma > 0.1f;
        const bool  ma_dn = ma < -0.1f;
        const float ma2 = ma_up ? 0.7f : 0.0f;
        const float ma0 = ma_dn ? 0.7f : 0.0f;

        const bool st_dn = ssig < -0.1f;
        const bool st_up = ssig > 0.1f;

        // OR of all 3-of-4 conjunctions == majority(>=3 of 4)
        const bool long_sig  = ((int)sb + (int)ma_up + (int)st_dn + (int)pp_lo) >= 3;
        const bool short_sig = ((int)sB + (int)ma_dn + (int)st_up + (int)pp_hi) >= 3;

        const float hms2 = long_sig  ? 0.9f : 0.0f;
        const float hms0 = short_sig ? 0.9f : 0.0f;

        const float col0 = ha0 + ma0 + st0 + bb0 + 2.0f * hms0;
        const float col2 = ha2 + ma2 + st2 + bb2 + 2.0f * hms2;
        const float col1 = 1.5f;

        const float m  = fmaxf(fmaxf(col0, col2), col1);
        const float e0 = __expf(col0 - m);
        const float e1 = __expf(col1 - m);
        const float e2 = __expf(col2 - m);
        const float inv = 1.0f / (e0 + e1 + e2);

        s_out[tid * 3 + 0] = e0 * inv;
        s_out[tid * 3 + 1] = e1 * inv;
        s_out[tid * 3 + 2] = e2 * inv;
    }
    __syncthreads();

    // ---- coalesced vectorized store ----
    const float4* so4 = (const float4*)s_out;
    const int obase = bid * OUT_F4;       // max 7812*192 = 1.5M
    if (bid < nfull) {
        if (tid < OUT_F4)                 // 192 of 256 threads
            out4[obase + tid] = so4[tid];
    } else {
        // tail: 128 rows -> 96 float4
        if (tid < 96) out4[obase + tid] = so4[tid];
    }
}

extern "C" void kernel_launch(void* const* d_in, const int* in_sizes, int n_in,
                              void* d_out, int out_size) {
    const float4* in4 = (const float4*)d_in[0];
    float4* out4 = (float4*)d_out;
    const int n = in_sizes[0] / NCOLS;       // 2,000,000 rows
    const int grid  = (n + RPB - 1) / RPB;   // 7813 blocks
    const int nfull = n / RPB;               // 7812 full blocks
    indicator_kernel<<<grid, T>>>(in4, out4, nfull, n);
}